// round 5
// baseline (speedup 1.0000x reference)
#include <cuda_runtime.h>
#include <cuda_bf16.h>

#define RANGE_MIN    (-5.0f)
#define RANGE_MAX    ( 5.0f)
#define MIN_BIN_SIZE (0.0001f)
#define MIN_SLOPE    (0.0001f)
#define KBINS        8

// Shared spline tables per block
struct SplineTab {
    float x_pos[KBINS + 1];
    float y_pos[KBINS + 1];
    float slopes[KBINS + 1];
    float logdet_left;
    float logdet_right;
};

__device__ __forceinline__ float softplusf(float z) {
    // log1p(exp(z)) with overflow guard
    return (z > 20.0f) ? z : log1pf(expf(z));
}

__global__ void __launch_bounds__(256) rqs_kernel(
    const float* __restrict__ x_in,
    const float* __restrict__ params,
    float* __restrict__ y_out,
    float* __restrict__ ld_out,
    int n)
{
    __shared__ SplineTab tab;

    if (threadIdx.x == 0) {
        // ---- normalize params (K widths, K heights, K+1 slopes) ----
        float w[KBINS], h[KBINS];
        const float total = RANGE_MAX - RANGE_MIN;
        const float scale = total - KBINS * MIN_BIN_SIZE;

        // softmax widths
        float m = -1e30f;
        #pragma unroll
        for (int i = 0; i < KBINS; i++) m = fmaxf(m, params[i]);
        float sum = 0.0f;
        #pragma unroll
        for (int i = 0; i < KBINS; i++) { w[i] = expf(params[i] - m); sum += w[i]; }
        float inv = 1.0f / sum;
        #pragma unroll
        for (int i = 0; i < KBINS; i++) w[i] = w[i] * inv * scale + MIN_BIN_SIZE;

        // softmax heights
        m = -1e30f;
        #pragma unroll
        for (int i = 0; i < KBINS; i++) m = fmaxf(m, params[KBINS + i]);
        sum = 0.0f;
        #pragma unroll
        for (int i = 0; i < KBINS; i++) { h[i] = expf(params[KBINS + i] - m); sum += h[i]; }
        inv = 1.0f / sum;
        #pragma unroll
        for (int i = 0; i < KBINS; i++) h[i] = h[i] * inv * scale + MIN_BIN_SIZE;

        // slopes: softplus(p + offset) + MIN_SLOPE, offset = log(exp(1-MIN_SLOPE)-1)
        const float off = logf(expf(1.0f - MIN_SLOPE) - 1.0f);
        #pragma unroll
        for (int i = 0; i < KBINS + 1; i++)
            tab.slopes[i] = softplusf(params[2 * KBINS + i] + off) + MIN_SLOPE;

        // cumsum positions
        float cx = 0.0f, cy = 0.0f;
        tab.x_pos[0] = RANGE_MIN;
        tab.y_pos[0] = RANGE_MIN;
        #pragma unroll
        for (int i = 0; i < KBINS; i++) {
            cx += w[i]; cy += h[i];
            tab.x_pos[i + 1] = cx + RANGE_MIN;
            tab.y_pos[i + 1] = cy + RANGE_MIN;
        }

        tab.logdet_left  = logf(tab.slopes[0]);
        tab.logdet_right = logf(tab.slopes[KBINS]);
    }
    __syncthreads();

    // copy table to registers (small, uniform — broadcast from shared)
    float xp[KBINS + 1], yp[KBINS + 1], sl[KBINS + 1];
    #pragma unroll
    for (int i = 0; i < KBINS + 1; i++) { xp[i] = tab.x_pos[i]; yp[i] = tab.y_pos[i]; sl[i] = tab.slopes[i]; }
    const float ld_left = tab.logdet_left;
    const float ld_right = tab.logdet_right;

    const int n4 = n >> 2;
    const float4* __restrict__ x4 = (const float4*)x_in;
    float4* __restrict__ y4 = (float4*)y_out;
    float4* __restrict__ l4 = (float4*)ld_out;

    for (int idx = blockIdx.x * blockDim.x + threadIdx.x; idx < n4;
         idx += gridDim.x * blockDim.x)
    {
        float4 xv = x4[idx];
        float xs[4] = {xv.x, xv.y, xv.z, xv.w};
        float ys[4], ls[4];

        #pragma unroll
        for (int e = 0; e < 4; e++) {
            float x = xs[e];

            // bin index: count of interior knots <= x  (searchsorted 'right')
            int b = 0;
            #pragma unroll
            for (int j = 1; j < KBINS; j++) b += (x >= xp[j]) ? 1 : 0;

            float x_k  = xp[b];
            float x_k1 = xp[b + 1];
            float y_k  = yp[b];
            float y_k1 = yp[b + 1];
            float s_k  = sl[b];
            float s_k1 = sl[b + 1];

            float width  = x_k1 - x_k;
            float height = y_k1 - y_k;
            float xi = (x - x_k) / width;
            xi = fminf(fmaxf(xi, 0.0f), 1.0f);
            float s = height / width;

            float xi1m  = 1.0f - xi;
            float t     = xi * xi1m;        // xi*(1-xi)
            float xi2   = xi * xi;

            float num = s * xi2 + s_k * t;
            float den = s + (s_k1 + s_k - 2.0f * s) * t;
            float y_spline = y_k + height * num / den;

            float numd = s * s * (s_k1 * xi2 + 2.0f * s * t + s_k * xi1m * xi1m);
            float deriv = numd / (den * den);
            float ld_spline = logf(deriv);

            bool below = x < RANGE_MIN;
            bool above = x > RANGE_MAX;

            float y_lin_l = (x - RANGE_MIN) * sl[0]     + RANGE_MIN;
            float y_lin_r = (x - RANGE_MAX) * sl[KBINS] + RANGE_MAX;

            float y  = below ? y_lin_l : (above ? y_lin_r : y_spline);
            float ld = below ? ld_left : (above ? ld_right : ld_spline);

            ys[e] = y;
            ls[e] = ld;
        }

        y4[idx] = make_float4(ys[0], ys[1], ys[2], ys[3]);
        l4[idx] = make_float4(ls[0], ls[1], ls[2], ls[3]);
    }
}

extern "C" void kernel_launch(void* const* d_in, const int* in_sizes, int n_in,
                              void* d_out, int out_size) {
    const float* x      = (const float*)d_in[0];
    const float* params = (const float*)d_in[1];
    int n = in_sizes[0];
    float* y  = (float*)d_out;
    float* ld = (float*)d_out + n;

    const int threads = 256;
    int n4 = n >> 2;
    int blocks = (n4 + threads * 8 - 1) / (threads * 8);   // ~8 float4 per thread
    if (blocks < 1) blocks = 1;
    if (blocks > 65535 * 8) blocks = 65535 * 8;
    rqs_kernel<<<blocks, threads>>>(x, params, y, ld, n);
}

// round 6
// speedup vs baseline: 1.5880x; 1.5880x over previous
#include <cuda_runtime.h>
#include <cuda_bf16.h>

#define RANGE_MIN    (-5.0f)
#define RANGE_MAX    ( 5.0f)
#define MIN_BIN_SIZE (0.0001f)
#define MIN_SLOPE    (0.0001f)
#define KBINS        8

__device__ __forceinline__ float softplusf(float z) {
    return (z > 20.0f) ? z : log1pf(expf(z));
}

__global__ void __launch_bounds__(256) rqs_kernel(
    const float* __restrict__ x_in,
    const float* __restrict__ params,
    float* __restrict__ y_out,
    float* __restrict__ ld_out,
    int n)
{
    // Per-bin derived constants, gathered with LDS.128 (16B stride -> <=2-way conflicts)
    __shared__ float4 tabA[KBINS];        // {x_k, inv_w, y_k, h}
    __shared__ float4 tabB[KBINS];        // {s_k, s_k1, s, d2}  d2 = s_k+s_k1-2s
    __shared__ float  knots[KBINS + 1];   // x_pos
    __shared__ float  misc[4];            // sl0, slK, ld_left, ld_right

    if (threadIdx.x == 0) {
        float w[KBINS], h[KBINS], sl[KBINS + 1];
        const float total = RANGE_MAX - RANGE_MIN;
        const float scale = total - KBINS * MIN_BIN_SIZE;

        // softmax widths
        float m = -1e30f;
        #pragma unroll
        for (int i = 0; i < KBINS; i++) m = fmaxf(m, params[i]);
        float sum = 0.0f;
        #pragma unroll
        for (int i = 0; i < KBINS; i++) { w[i] = expf(params[i] - m); sum += w[i]; }
        float inv = 1.0f / sum;
        #pragma unroll
        for (int i = 0; i < KBINS; i++) w[i] = w[i] * inv * scale + MIN_BIN_SIZE;

        // softmax heights
        m = -1e30f;
        #pragma unroll
        for (int i = 0; i < KBINS; i++) m = fmaxf(m, params[KBINS + i]);
        sum = 0.0f;
        #pragma unroll
        for (int i = 0; i < KBINS; i++) { h[i] = expf(params[KBINS + i] - m); sum += h[i]; }
        inv = 1.0f / sum;
        #pragma unroll
        for (int i = 0; i < KBINS; i++) h[i] = h[i] * inv * scale + MIN_BIN_SIZE;

        // slopes
        const float off = logf(expf(1.0f - MIN_SLOPE) - 1.0f);
        #pragma unroll
        for (int i = 0; i < KBINS + 1; i++)
            sl[i] = softplusf(params[2 * KBINS + i] + off) + MIN_SLOPE;

        // knot positions (cumsum) + per-bin derived values
        float xpos[KBINS + 1], ypos[KBINS + 1];
        xpos[0] = RANGE_MIN; ypos[0] = RANGE_MIN;
        float cx = 0.0f, cy = 0.0f;
        #pragma unroll
        for (int i = 0; i < KBINS; i++) {
            cx += w[i]; cy += h[i];
            xpos[i + 1] = cx + RANGE_MIN;
            ypos[i + 1] = cy + RANGE_MIN;
        }
        #pragma unroll
        for (int i = 0; i < KBINS + 1; i++) knots[i] = xpos[i];

        #pragma unroll
        for (int b = 0; b < KBINS; b++) {
            float width  = xpos[b + 1] - xpos[b];
            float height = ypos[b + 1] - ypos[b];
            float inv_w  = 1.0f / width;
            float s      = height * inv_w;
            tabA[b] = make_float4(xpos[b], inv_w, ypos[b], height);
            tabB[b] = make_float4(sl[b], sl[b + 1], s, sl[b] + sl[b + 1] - 2.0f * s);
        }

        misc[0] = sl[0];
        misc[1] = sl[KBINS];
        misc[2] = logf(sl[0]);
        misc[3] = logf(sl[KBINS]);
    }
    __syncthreads();

    // interior knots -> registers (uniform broadcast, static indices only)
    float kp[KBINS - 1];
    #pragma unroll
    for (int j = 0; j < KBINS - 1; j++) kp[j] = knots[j + 1];
    const float sl0      = misc[0];
    const float slK      = misc[1];
    const float ld_left  = misc[2];
    const float ld_right = misc[3];

    const int n4 = n >> 2;
    const float4* __restrict__ x4 = (const float4*)x_in;
    float4* __restrict__ y4 = (float4*)y_out;
    float4* __restrict__ l4 = (float4*)ld_out;

    for (int idx = blockIdx.x * blockDim.x + threadIdx.x; idx < n4;
         idx += gridDim.x * blockDim.x)
    {
        float4 xv = x4[idx];
        float xs[4] = {xv.x, xv.y, xv.z, xv.w};
        float ys[4], ls[4];

        #pragma unroll
        for (int e = 0; e < 4; e++) {
            float x = xs[e];

            // searchsorted(x_pos[1:-1], x, 'right'), clipped to [0, K-1]
            int b = 0;
            #pragma unroll
            for (int j = 0; j < KBINS - 1; j++) b += (x >= kp[j]) ? 1 : 0;

            float4 A = tabA[b];   // x_k, inv_w, y_k, h
            float4 B = tabB[b];   // s_k, s_k1, s, d2

            float xi = (x - A.x) * A.y;
            xi = fminf(fmaxf(xi, 0.0f), 1.0f);

            float xi1m = 1.0f - xi;
            float t    = xi * xi1m;
            float xi2  = xi * xi;

            float num  = B.z * xi2 + B.x * t;
            float den  = B.z + B.w * t;
            float rden = __fdividef(1.0f, den);

            float y_spline = fmaf(A.w * num, rden, A.z);

            float numd  = B.z * B.z * (B.y * xi2 + 2.0f * B.z * t + B.x * xi1m * xi1m);
            float deriv = numd * rden * rden;
            float ld_spline = __logf(deriv);

            bool below = x < RANGE_MIN;
            bool above = x > RANGE_MAX;

            float y_lin_l = fmaf(x - RANGE_MIN, sl0, RANGE_MIN);
            float y_lin_r = fmaf(x - RANGE_MAX, slK, RANGE_MAX);

            ys[e] = below ? y_lin_l : (above ? y_lin_r : y_spline);
            ls[e] = below ? ld_left : (above ? ld_right : ld_spline);
        }

        y4[idx] = make_float4(ys[0], ys[1], ys[2], ys[3]);
        l4[idx] = make_float4(ls[0], ls[1], ls[2], ls[3]);
    }
}

extern "C" void kernel_launch(void* const* d_in, const int* in_sizes, int n_in,
                              void* d_out, int out_size) {
    const float* x      = (const float*)d_in[0];
    const float* params = (const float*)d_in[1];
    int n = in_sizes[0];
    float* y  = (float*)d_out;
    float* ld = (float*)d_out + n;

    const int threads = 256;
    int n4 = n >> 2;
    int blocks = (n4 + threads * 8 - 1) / (threads * 8);   // ~8 float4 per thread
    if (blocks < 1) blocks = 1;
    rqs_kernel<<<blocks, threads>>>(x, params, y, ld, n);
}

// round 8
// speedup vs baseline: 1.6121x; 1.0152x over previous
#include <cuda_runtime.h>
#include <cuda_bf16.h>
#include <math_constants.h>

#define RANGE_MIN    (-5.0f)
#define RANGE_MAX    ( 5.0f)
#define MIN_BIN_SIZE (0.0001f)
#define MIN_SLOPE    (0.0001f)
#define KBINS        8
#define NCELLS       512
#define CELL_SCALE   (NCELLS / (RANGE_MAX - RANGE_MIN))   // 51.2

__device__ __forceinline__ float softplusf(float z) {
    return (z > 20.0f) ? z : log1pf(expf(z));
}

__global__ void __launch_bounds__(256) rqs_kernel(
    const float* __restrict__ x_in,
    const float* __restrict__ params,
    float* __restrict__ y_out,
    float* __restrict__ ld_out,
    int n)
{
    // Interleaved per-bin record (32B): {x_k, inv_w, y_k, h | s_k, s_k1, s, d2}
    __shared__ float4 tab[2 * KBINS];
    __shared__ float2 knotpair[KBINS];     // {knot[b+1], knot[b+2]} (+INF padded)
    __shared__ float  ikn[KBINS + 2];      // interior knots ikn[1..7], [8],[9]=+INF
    __shared__ float  misc[4];             // sl0, slK, ld_left, ld_right
    __shared__ unsigned char lut[NCELLS];  // cell -> bin of cell lower edge

    if (threadIdx.x == 0) {
        float w[KBINS], h[KBINS], sl[KBINS + 1];
        const float total = RANGE_MAX - RANGE_MIN;
        const float scale = total - KBINS * MIN_BIN_SIZE;

        // softmax widths
        float m = -1e30f;
        #pragma unroll
        for (int i = 0; i < KBINS; i++) m = fmaxf(m, params[i]);
        float sum = 0.0f;
        #pragma unroll
        for (int i = 0; i < KBINS; i++) { w[i] = expf(params[i] - m); sum += w[i]; }
        float inv = 1.0f / sum;
        #pragma unroll
        for (int i = 0; i < KBINS; i++) w[i] = w[i] * inv * scale + MIN_BIN_SIZE;

        // softmax heights
        m = -1e30f;
        #pragma unroll
        for (int i = 0; i < KBINS; i++) m = fmaxf(m, params[KBINS + i]);
        sum = 0.0f;
        #pragma unroll
        for (int i = 0; i < KBINS; i++) { h[i] = expf(params[KBINS + i] - m); sum += h[i]; }
        inv = 1.0f / sum;
        #pragma unroll
        for (int i = 0; i < KBINS; i++) h[i] = h[i] * inv * scale + MIN_BIN_SIZE;

        // slopes
        const float off = logf(expf(1.0f - MIN_SLOPE) - 1.0f);
        #pragma unroll
        for (int i = 0; i < KBINS + 1; i++)
            sl[i] = softplusf(params[2 * KBINS + i] + off) + MIN_SLOPE;

        // cumsum knots + derived per-bin record
        float xpos[KBINS + 1], ypos[KBINS + 1];
        xpos[0] = RANGE_MIN; ypos[0] = RANGE_MIN;
        float cx = 0.0f, cy = 0.0f;
        #pragma unroll
        for (int i = 0; i < KBINS; i++) {
            cx += w[i]; cy += h[i];
            xpos[i + 1] = cx + RANGE_MIN;
            ypos[i + 1] = cy + RANGE_MIN;
        }

        #pragma unroll
        for (int b = 0; b < KBINS; b++) {
            float width  = xpos[b + 1] - xpos[b];
            float height = ypos[b + 1] - ypos[b];
            float inv_w  = 1.0f / width;
            float s      = height * inv_w;
            tab[2 * b]     = make_float4(xpos[b], inv_w, ypos[b], height);
            tab[2 * b + 1] = make_float4(sl[b], sl[b + 1], s, sl[b] + sl[b + 1] - 2.0f * s);
        }

        // interior knots with +INF sentinels; correction pairs
        #pragma unroll
        for (int j = 1; j < KBINS; j++) ikn[j] = xpos[j];
        ikn[KBINS] = CUDART_INF_F;      // index 8
        ikn[KBINS + 1] = CUDART_INF_F;  // index 9
        #pragma unroll
        for (int b = 0; b < KBINS; b++)
            knotpair[b] = make_float2(ikn[b + 1], ikn[b + 2]);

        misc[0] = sl[0];
        misc[1] = sl[KBINS];
        misc[2] = logf(sl[0]);
        misc[3] = logf(sl[KBINS]);
    }
    __syncthreads();

    // parallel LUT build: bin of each cell's lower edge
    {
        float k1 = ikn[1], k2 = ikn[2], k3 = ikn[3], k4 = ikn[4],
              k5 = ikn[5], k6 = ikn[6], k7 = ikn[7];
        for (int c = threadIdx.x; c < NCELLS; c += blockDim.x) {
            float cs = RANGE_MIN + (float)c * ((RANGE_MAX - RANGE_MIN) / NCELLS);
            int b = 0;
            b += (cs >= k1); b += (cs >= k2); b += (cs >= k3); b += (cs >= k4);
            b += (cs >= k5); b += (cs >= k6); b += (cs >= k7);
            lut[c] = (unsigned char)b;
        }
    }
    __syncthreads();

    const float sl0      = misc[0];
    const float slK      = misc[1];
    const float ld_left  = misc[2];
    const float ld_right = misc[3];

    const int n4 = n >> 2;
    const float4* __restrict__ x4 = (const float4*)x_in;
    float4* __restrict__ y4 = (float4*)y_out;
    float4* __restrict__ l4 = (float4*)ld_out;

    for (int idx = blockIdx.x * blockDim.x + threadIdx.x; idx < n4;
         idx += gridDim.x * blockDim.x)
    {
        float4 xv = __ldcs(&x4[idx]);
        float xs[4] = {xv.x, xv.y, xv.z, xv.w};
        float ys[4], ls[4];

        #pragma unroll
        for (int e = 0; e < 4; e++) {
            float x = xs[e];

            // cell -> candidate bin -> <=2 corrections
            int c = (int)fmaf(x, CELL_SCALE, (float)(NCELLS / 2));
            c = min(max(c, 0), NCELLS - 1);
            int b = (int)lut[c];
            float2 kk = knotpair[b];
            b += (x >= kk.x);
            b += (x >= kk.y);

            float4 A = tab[2 * b];       // x_k, inv_w, y_k, h
            float4 B = tab[2 * b + 1];   // s_k, s_k1, s, d2

            float xi = (x - A.x) * A.y;
            xi = fminf(fmaxf(xi, 0.0f), 1.0f);

            float xi1m = 1.0f - xi;
            float t    = xi * xi1m;
            float xi2  = xi * xi;

            float num  = B.z * xi2 + B.x * t;
            float den  = fmaf(B.w, t, B.z);
            float rden = __fdividef(1.0f, den);

            float y_spline = fmaf(A.w * num, rden, A.z);

            float numd  = B.z * B.z * (B.y * xi2 + 2.0f * B.z * t + B.x * xi1m * xi1m);
            float deriv = numd * rden * rden;
            float ld_spline = __logf(deriv);

            bool below = x < RANGE_MIN;
            bool above = x > RANGE_MAX;

            float y_lin_l = fmaf(x - RANGE_MIN, sl0, RANGE_MIN);
            float y_lin_r = fmaf(x - RANGE_MAX, slK, RANGE_MAX);

            ys[e] = below ? y_lin_l : (above ? y_lin_r : y_spline);
            ls[e] = below ? ld_left : (above ? ld_right : ld_spline);
        }

        __stcs(&y4[idx], make_float4(ys[0], ys[1], ys[2], ys[3]));
        __stcs(&l4[idx], make_float4(ls[0], ls[1], ls[2], ls[3]));
    }
}

extern "C" void kernel_launch(void* const* d_in, const int* in_sizes, int n_in,
                              void* d_out, int out_size) {
    const float* x      = (const float*)d_in[0];
    const float* params = (const float*)d_in[1];
    int n = in_sizes[0];
    float* y  = (float*)d_out;
    float* ld = (float*)d_out + n;

    const int threads = 256;
    int n4 = n >> 2;
    int blocks = (n4 + threads * 8 - 1) / (threads * 8);   // ~8 float4 per thread
    if (blocks < 1) blocks = 1;
    rqs_kernel<<<blocks, threads>>>(x, params, y, ld, n);
}

// round 10
// speedup vs baseline: 1.7711x; 1.0987x over previous
#include <cuda_runtime.h>
#include <cuda_bf16.h>
#include <math_constants.h>

#define RANGE_MIN    (-5.0f)
#define RANGE_MAX    ( 5.0f)
#define MIN_BIN_SIZE (0.0001f)
#define MIN_SLOPE    (0.0001f)
#define KBINS        8
#define NCELLS       512
#define CELL_SCALE   (NCELLS / (RANGE_MAX - RANGE_MIN))   // 51.2

__device__ __forceinline__ float softplusf(float z) {
    return (z > 20.0f) ? z : log1pf(expf(z));
}

struct Tables {
    float4 tab[2 * KBINS];            // {x_k, inv_w, y_k, h | s_k, s_k1, s, d2}
    float2 knotpair[KBINS];           // {knot[b+1], knot[b+2]} (+INF padded)
    float  ikn[KBINS + 2];
    float  misc[4];                   // sl0, slK, ld_left, ld_right
    unsigned char lut[NCELLS];
};

__device__ __forceinline__ void rqs_eval(
    float x, const Tables& T,
    float sl0, float slK, float ld_left, float ld_right,
    float& y_o, float& ld_o)
{
    int c = (int)fmaf(x, CELL_SCALE, (float)(NCELLS / 2));
    c = min(max(c, 0), NCELLS - 1);
    int b = (int)T.lut[c];
    float2 kk = T.knotpair[b];
    b += (x >= kk.x);
    b += (x >= kk.y);

    float4 A = T.tab[2 * b];       // x_k, inv_w, y_k, h
    float4 B = T.tab[2 * b + 1];   // s_k, s_k1, s, d2

    float xi = (x - A.x) * A.y;
    xi = fminf(fmaxf(xi, 0.0f), 1.0f);

    float xi1m = 1.0f - xi;
    float t    = xi * xi1m;
    float xi2  = xi * xi;

    float num  = B.z * xi2 + B.x * t;
    float den  = fmaf(B.w, t, B.z);
    float rden = __fdividef(1.0f, den);

    float y_spline = fmaf(A.w * num, rden, A.z);

    float numd  = B.z * B.z * (B.y * xi2 + 2.0f * B.z * t + B.x * xi1m * xi1m);
    float deriv = numd * rden * rden;
    float ld_spline = __logf(deriv);

    bool below = x < RANGE_MIN;
    bool above = x > RANGE_MAX;

    float y_lin_l = fmaf(x - RANGE_MIN, sl0, RANGE_MIN);
    float y_lin_r = fmaf(x - RANGE_MAX, slK, RANGE_MAX);

    y_o  = below ? y_lin_l : (above ? y_lin_r : y_spline);
    ld_o = below ? ld_left : (above ? ld_right : ld_spline);
}

__global__ void __launch_bounds__(256, 5) rqs_kernel(
    const float* __restrict__ x_in,
    const float* __restrict__ params,
    float* __restrict__ y_out,
    float* __restrict__ ld_out,
    int n)
{
    __shared__ Tables T;

    if (threadIdx.x == 0) {
        float w[KBINS], h[KBINS], sl[KBINS + 1];
        const float total = RANGE_MAX - RANGE_MIN;
        const float scale = total - KBINS * MIN_BIN_SIZE;

        float m = -1e30f;
        #pragma unroll
        for (int i = 0; i < KBINS; i++) m = fmaxf(m, params[i]);
        float sum = 0.0f;
        #pragma unroll
        for (int i = 0; i < KBINS; i++) { w[i] = expf(params[i] - m); sum += w[i]; }
        float inv = 1.0f / sum;
        #pragma unroll
        for (int i = 0; i < KBINS; i++) w[i] = w[i] * inv * scale + MIN_BIN_SIZE;

        m = -1e30f;
        #pragma unroll
        for (int i = 0; i < KBINS; i++) m = fmaxf(m, params[KBINS + i]);
        sum = 0.0f;
        #pragma unroll
        for (int i = 0; i < KBINS; i++) { h[i] = expf(params[KBINS + i] - m); sum += h[i]; }
        inv = 1.0f / sum;
        #pragma unroll
        for (int i = 0; i < KBINS; i++) h[i] = h[i] * inv * scale + MIN_BIN_SIZE;

        const float off = logf(expf(1.0f - MIN_SLOPE) - 1.0f);
        #pragma unroll
        for (int i = 0; i < KBINS + 1; i++)
            sl[i] = softplusf(params[2 * KBINS + i] + off) + MIN_SLOPE;

        float xpos[KBINS + 1], ypos[KBINS + 1];
        xpos[0] = RANGE_MIN; ypos[0] = RANGE_MIN;
        float cx = 0.0f, cy = 0.0f;
        #pragma unroll
        for (int i = 0; i < KBINS; i++) {
            cx += w[i]; cy += h[i];
            xpos[i + 1] = cx + RANGE_MIN;
            ypos[i + 1] = cy + RANGE_MIN;
        }

        #pragma unroll
        for (int b = 0; b < KBINS; b++) {
            float width  = xpos[b + 1] - xpos[b];
            float height = ypos[b + 1] - ypos[b];
            float inv_w  = 1.0f / width;
            float s      = height * inv_w;
            T.tab[2 * b]     = make_float4(xpos[b], inv_w, ypos[b], height);
            T.tab[2 * b + 1] = make_float4(sl[b], sl[b + 1], s, sl[b] + sl[b + 1] - 2.0f * s);
        }

        #pragma unroll
        for (int j = 1; j < KBINS; j++) T.ikn[j] = xpos[j];
        T.ikn[KBINS] = CUDART_INF_F;
        T.ikn[KBINS + 1] = CUDART_INF_F;
        #pragma unroll
        for (int b = 0; b < KBINS; b++)
            T.knotpair[b] = make_float2(T.ikn[b + 1], T.ikn[b + 2]);

        T.misc[0] = sl[0];
        T.misc[1] = sl[KBINS];
        T.misc[2] = logf(sl[0]);
        T.misc[3] = logf(sl[KBINS]);
    }
    __syncthreads();

    {
        float k1 = T.ikn[1], k2 = T.ikn[2], k3 = T.ikn[3], k4 = T.ikn[4],
              k5 = T.ikn[5], k6 = T.ikn[6], k7 = T.ikn[7];
        for (int c = threadIdx.x; c < NCELLS; c += blockDim.x) {
            float cs = RANGE_MIN + (float)c * ((RANGE_MAX - RANGE_MIN) / NCELLS);
            int b = 0;
            b += (cs >= k1); b += (cs >= k2); b += (cs >= k3); b += (cs >= k4);
            b += (cs >= k5); b += (cs >= k6); b += (cs >= k7);
            T.lut[c] = (unsigned char)b;
        }
    }
    __syncthreads();

    const float sl0      = T.misc[0];
    const float slK      = T.misc[1];
    const float ld_left  = T.misc[2];
    const float ld_right = T.misc[3];

    const int n4 = n >> 2;
    const float4* __restrict__ x4 = (const float4*)x_in;
    float4* __restrict__ y4 = (float4*)y_out;
    float4* __restrict__ l4 = (float4*)ld_out;

    const int stride = gridDim.x * blockDim.x;
    int idx = blockIdx.x * blockDim.x + threadIdx.x;

    // main loop: 2 independent float4 loads in flight per iteration
    for (; idx + stride < n4; idx += 2 * stride) {
        float4 xa = __ldcs(&x4[idx]);
        float4 xb = __ldcs(&x4[idx + stride]);

        float4 ya, la, yb, lb;
        rqs_eval(xa.x, T, sl0, slK, ld_left, ld_right, ya.x, la.x);
        rqs_eval(xa.y, T, sl0, slK, ld_left, ld_right, ya.y, la.y);
        rqs_eval(xa.z, T, sl0, slK, ld_left, ld_right, ya.z, la.z);
        rqs_eval(xa.w, T, sl0, slK, ld_left, ld_right, ya.w, la.w);

        __stcs(&y4[idx], ya);
        __stcs(&l4[idx], la);

        rqs_eval(xb.x, T, sl0, slK, ld_left, ld_right, yb.x, lb.x);
        rqs_eval(xb.y, T, sl0, slK, ld_left, ld_right, yb.y, lb.y);
        rqs_eval(xb.z, T, sl0, slK, ld_left, ld_right, yb.z, lb.z);
        rqs_eval(xb.w, T, sl0, slK, ld_left, ld_right, yb.w, lb.w);

        __stcs(&y4[idx + stride], yb);
        __stcs(&l4[idx + stride], lb);
    }
    // tail (single float4)
    for (; idx < n4; idx += stride) {
        float4 xa = __ldcs(&x4[idx]);
        float4 ya, la;
        rqs_eval(xa.x, T, sl0, slK, ld_left, ld_right, ya.x, la.x);
        rqs_eval(xa.y, T, sl0, slK, ld_left, ld_right, ya.y, la.y);
        rqs_eval(xa.z, T, sl0, slK, ld_left, ld_right, ya.z, la.z);
        rqs_eval(xa.w, T, sl0, slK, ld_left, ld_right, ya.w, la.w);
        __stcs(&y4[idx], ya);
        __stcs(&l4[idx], la);
    }
}

extern "C" void kernel_launch(void* const* d_in, const int* in_sizes, int n_in,
                              void* d_out, int out_size) {
    const float* x      = (const float*)d_in[0];
    const float* params = (const float*)d_in[1];
    int n = in_sizes[0];
    float* y  = (float*)d_out;
    float* ld = (float*)d_out + n;

    const int threads = 256;
    int n4 = n >> 2;
    int blocks = (n4 + threads * 8 - 1) / (threads * 8);   // 8 float4 per thread
    if (blocks < 1) blocks = 1;
    rqs_kernel<<<blocks, threads>>>(x, params, y, ld, n);
}